// round 2
// baseline (speedup 1.0000x reference)
#include <cuda_runtime.h>

// Fused Bayer demosaic (see R1 notes for quadrant->stencil decode):
//   q0 (i even, j even): (diag, plus, center)
//   q1 (i even, j odd ): (vavg, center, havg)
//   q2 (i odd , j even): (havg, center, vavg)
//   q3 (i odd , j odd ): (center, plus, diag)
//
// R2: 8 px/thread (2x float4 loads per row, 2x float4 streaming stores per
// channel), __stcs on output so the write-once stream is evict-first in L2,
// preserving the 3x vertically-reused input rows.

__device__ __forceinline__ void load_row10(const float* __restrict__ r,
                                           int j0, int W, bool fast,
                                           float v[10]) {
    if (fast) {
        float4 m0 = *reinterpret_cast<const float4*>(r + j0);
        float4 m1 = *reinterpret_cast<const float4*>(r + j0 + 4);
        v[0] = __ldg(r + j0 - 1);
        v[1] = m0.x; v[2] = m0.y; v[3] = m0.z; v[4] = m0.w;
        v[5] = m1.x; v[6] = m1.y; v[7] = m1.z; v[8] = m1.w;
        v[9] = __ldg(r + j0 + 8);
    } else {
#pragma unroll
        for (int k = 0; k < 10; ++k) {
            int c = j0 + k - 1;
            c = (c < 0) ? -c : c;                 // reflect: -1 -> 1
            c = (c >= W) ? (2 * W - 2 - c) : c;   // reflect: W -> W-2
            v[k] = __ldg(r + c);
        }
    }
}

__global__ __launch_bounds__(256) void bayer_demosaic_kernel(
    const float* __restrict__ x, float* __restrict__ y, int H, int W) {
    const int j0 = (blockIdx.x * blockDim.x + threadIdx.x) * 8;
    const int i  = blockIdx.y;
    const int n  = blockIdx.z;
    if (j0 >= W) return;

    const size_t plane = (size_t)H * W;
    const float* xp = x + (size_t)n * plane;

    const int im1 = (i == 0)     ? 1     : i - 1;   // reflect rows
    const int ip1 = (i == H - 1) ? H - 2 : i + 1;

    const float* ra = xp + (size_t)im1 * W;  // row above
    const float* rb = xp + (size_t)i   * W;  // center row
    const float* rc = xp + (size_t)ip1 * W;  // row below

    const bool fast = (j0 > 0) && (j0 + 8 < W);

    float a[10], b[10], c[10];
    load_row10(ra, j0, W, fast, a);
    load_row10(rb, j0, W, fast, b);
    load_row10(rc, j0, W, fast, c);

    float R[8], G[8], B[8];
    const int ip = i & 1;
#pragma unroll
    for (int t = 0; t < 8; ++t) {
        const float center = b[t + 1];
        const float plus   = 0.25f * ((a[t + 1] + c[t + 1]) + (b[t] + b[t + 2]));
        const float diag   = 0.25f * ((a[t] + a[t + 2]) + (c[t] + c[t + 2]));
        const float havg   = 0.5f  * (b[t] + b[t + 2]);
        const float vavg   = 0.5f  * (a[t + 1] + c[t + 1]);
        const int jp = t & 1;  // j0 is a multiple of 8 -> parity of j == parity of t
        if (ip == 0) {
            if (jp == 0) { R[t] = diag;   G[t] = plus;   B[t] = center; }  // q0
            else         { R[t] = vavg;   G[t] = center; B[t] = havg;   }  // q1
        } else {
            if (jp == 0) { R[t] = havg;   G[t] = center; B[t] = vavg;   }  // q2
            else         { R[t] = center; G[t] = plus;   B[t] = diag;   }  // q3
        }
    }

    float* yn = y + (size_t)n * 3 * plane + (size_t)i * W + j0;
    __stcs(reinterpret_cast<float4*>(yn),                 make_float4(R[0], R[1], R[2], R[3]));
    __stcs(reinterpret_cast<float4*>(yn + 4),             make_float4(R[4], R[5], R[6], R[7]));
    __stcs(reinterpret_cast<float4*>(yn + plane),         make_float4(G[0], G[1], G[2], G[3]));
    __stcs(reinterpret_cast<float4*>(yn + plane + 4),     make_float4(G[4], G[5], G[6], G[7]));
    __stcs(reinterpret_cast<float4*>(yn + 2 * plane),     make_float4(B[0], B[1], B[2], B[3]));
    __stcs(reinterpret_cast<float4*>(yn + 2 * plane + 4), make_float4(B[4], B[5], B[6], B[7]));
}

extern "C" void kernel_launch(void* const* d_in, const int* in_sizes, int n_in,
                              void* d_out, int out_size) {
    const float* x = (const float*)d_in[0];
    float* y = (float*)d_out;

    const int H = 4096, W = 4096;
    const int N = in_sizes[0] / (H * W);  // = 2

    dim3 block(256, 1, 1);
    dim3 grid((W / 8 + 255) / 256, H, N);
    bayer_demosaic_kernel<<<grid, block>>>(x, y, H, W);
}

// round 3
// speedup vs baseline: 1.2390x; 1.2390x over previous
#include <cuda_runtime.h>

// Fused Bayer demosaic. Quadrant -> (R,G,B) stencil map:
//   q0 (i even, j even): (diag, plus, center)
//   q1 (i even, j odd ): (vavg, center, havg)
//   q2 (i odd , j even): (havg, center, vavg)
//   q3 (i odd , j odd ): (center, plus, diag)
//
// R3 = R1 shape (4 px/thread, high occupancy for DRAM MLP) + __stcs
// streaming stores only. Single-variable test of evict-first output stores.

__device__ __forceinline__ void load_row6(const float* __restrict__ r,
                                          int j0, int W, bool fast,
                                          float v[6]) {
    if (fast) {
        float4 m = *reinterpret_cast<const float4*>(r + j0);
        v[0] = __ldg(r + j0 - 1);
        v[1] = m.x; v[2] = m.y; v[3] = m.z; v[4] = m.w;
        v[5] = __ldg(r + j0 + 4);
    } else {
#pragma unroll
        for (int k = 0; k < 6; ++k) {
            int c = j0 + k - 1;
            c = (c < 0) ? -c : c;                 // reflect: -1 -> 1
            c = (c >= W) ? (2 * W - 2 - c) : c;   // reflect: W -> W-2
            v[k] = __ldg(r + c);
        }
    }
}

__global__ __launch_bounds__(256) void bayer_demosaic_kernel(
    const float* __restrict__ x, float* __restrict__ y, int H, int W) {
    const int j0 = (blockIdx.x * blockDim.x + threadIdx.x) * 4;
    const int i  = blockIdx.y;
    const int n  = blockIdx.z;
    if (j0 >= W) return;

    const size_t plane = (size_t)H * W;
    const float* xp = x + (size_t)n * plane;

    const int im1 = (i == 0)     ? 1     : i - 1;   // reflect rows
    const int ip1 = (i == H - 1) ? H - 2 : i + 1;

    const float* ra = xp + (size_t)im1 * W;  // row above
    const float* rb = xp + (size_t)i   * W;  // center row
    const float* rc = xp + (size_t)ip1 * W;  // row below

    const bool fast = (j0 > 0) && (j0 + 4 < W);

    float a[6], b[6], c[6];
    load_row6(ra, j0, W, fast, a);
    load_row6(rb, j0, W, fast, b);
    load_row6(rc, j0, W, fast, c);

    float R[4], G[4], B[4];
    const int ip = i & 1;
#pragma unroll
    for (int t = 0; t < 4; ++t) {
        const float center = b[t + 1];
        const float plus   = 0.25f * ((a[t + 1] + c[t + 1]) + (b[t] + b[t + 2]));
        const float diag   = 0.25f * ((a[t] + a[t + 2]) + (c[t] + c[t + 2]));
        const float havg   = 0.5f  * (b[t] + b[t + 2]);
        const float vavg   = 0.5f  * (a[t + 1] + c[t + 1]);
        const int jp = t & 1;  // j0 multiple of 4 -> parity of j == parity of t
        if (ip == 0) {
            if (jp == 0) { R[t] = diag;   G[t] = plus;   B[t] = center; }  // q0
            else         { R[t] = vavg;   G[t] = center; B[t] = havg;   }  // q1
        } else {
            if (jp == 0) { R[t] = havg;   G[t] = center; B[t] = vavg;   }  // q2
            else         { R[t] = center; G[t] = plus;   B[t] = diag;   }  // q3
        }
    }

    float* yn = y + (size_t)n * 3 * plane + (size_t)i * W + j0;
    __stcs(reinterpret_cast<float4*>(yn),             make_float4(R[0], R[1], R[2], R[3]));
    __stcs(reinterpret_cast<float4*>(yn + plane),     make_float4(G[0], G[1], G[2], G[3]));
    __stcs(reinterpret_cast<float4*>(yn + 2 * plane), make_float4(B[0], B[1], B[2], B[3]));
}

extern "C" void kernel_launch(void* const* d_in, const int* in_sizes, int n_in,
                              void* d_out, int out_size) {
    const float* x = (const float*)d_in[0];
    float* y = (float*)d_out;

    const int H = 4096, W = 4096;
    const int N = in_sizes[0] / (H * W);  // = 2

    dim3 block(256, 1, 1);
    dim3 grid((W / 4 + 255) / 256, H, N);
    bayer_demosaic_kernel<<<grid, block>>>(x, y, H, W);
}